// round 10
// baseline (speedup 1.0000x reference)
#include <cuda_runtime.h>
#include <math.h>

#define AA 48
#define NDP 1128        // nondiag pairs
#define STEPS 23
#define ROW 1176        // AA + NDP
#define BPB 2           // batches per block
#define THREADS 320
#define Q4 (ROW / 4)    // 294 column-groups (one per thread)
#define LUTW 7          // cls = u'i + u'j in 0..6, u' in {0,1,3}
#define LSZ (Q4 * LUTW) // sub-table size (2058 floats)
#define WPR 16          // words per state row: [pad][12 data words][3 pad]

// interleaved LUT: entry (k, cls) at (k&3)*LSZ + (k>>2)*LUTW + cls
__device__ float g_lut[ROW * LUTW];
__device__ int   g_pair[NDP];        // iy | (ix<<8)

__global__ void setup_kernel(const float* __restrict__ ed,
                             const float* __restrict__ en) {
    int k = blockIdx.x * blockDim.x + threadIdx.x;
    if (k < AA) {
        // diag column k: i -> zero pad, so cls = u'j in {0,1,3}
        float s = 1.f / (1.f + expf(-ed[k]));
        float* L = &g_lut[(k & 3) * LSZ + (k >> 2) * LUTW];
        #pragma unroll
        for (int c = 0; c < LUTW; ++c) L[c] = 0.f;
        L[1] = s;     // st == 0
        L[3] = 1.f;   // st == 1
    }
    if (k < NDP) {
        float f12 = 1.f / (1.f + expf(-en[k * 4 + 0]));
        float f9  = 1.f / (1.f + expf(-en[k * 4 + 1])) * f12;
        float f8  = 1.f / (1.f + expf(-en[k * 4 + 2])) * f9;
        float f6  = 1.f / (1.f + expf(-en[k * 4 + 3])) * f8;
        // u' in {0,1,3}: cls -> 0:0  1:f6  2:f9  3:f8  4:f12  6:1
        int kk = AA + k;
        float* L = &g_lut[(kk & 3) * LSZ + (kk >> 2) * LUTW];
        L[0] = 0.f; L[1] = f6;  L[2] = f9;
        L[3] = f8;  L[4] = f12; L[5] = 0.f;
        L[6] = 1.f;
        int rem = k, iy = 0;
        while (rem >= AA - 1 - iy) { rem -= AA - 1 - iy; ++iy; }
        int ix = iy + 1 + rem;
        g_pair[k] = iy | (ix << 8);
    }
}

__global__ __launch_bounds__(THREADS, 6)
void main_kernel(const int* __restrict__ x, float* __restrict__ out) {
    __shared__ unsigned int s_state[BPB * STEPS * WPR];     // 2944 B

    const int tid = threadIdx.x;
    const int b0  = blockIdx.x * BPB;

    // ---- zero pad words (front word 0, back words 13,14,15 of each row) ----
    if (tid < BPB * STEPS * 4) {
        int q  = tid / (STEPS * 4);
        int rr = tid - q * (STEPS * 4);
        int r  = rr >> 2;
        int w  = rr & 3;
        int word = (w == 0) ? 0 : (12 + w);
        s_state[(q * STEPS + r) * WPR + word] = 0u;
    }

    // ---- phase 1: integer recurrence, one thread per (q, column) ----
    if (tid < BPB * AA) {
        int q = tid / AA;
        int j = tid - q * AA;
        const int* xb = x + (long)(b0 + q) * (25 * AA) + j;
        unsigned int v = 0;
        #pragma unroll
        for (int r = 0; r < 25; ++r)
            v |= ((unsigned int)__ldg(xb + r * AA)) << r;

        unsigned char* sb = reinterpret_cast<unsigned char*>(s_state);
        int st = -1, dt = 1;
        #pragma unroll
        for (int r = 0; r < STEPS; ++r) {
            int a  = (v >> r)       & 1;
            int bb = (v >> (r + 1)) & 1;
            int c  = (v >> (r + 2)) & 1;
            int de = a ^ c;
            int me = bb * (1 - (a + c)) + a * c;
            dt = dt * (1 - 2 * me);
            st = st + dt * de;
            st = st < -1 ? -1 : (st > 1 ? 1 : st);
            int ome = 1 - me;
            dt = dt * (1 - st * st * ome) - st * ome;
            int u = st + 1;                 // 0,1,2
            u = u + (u >> 1);               // remap 2 -> 3 : u' in {0,1,3}
            sb[((q * STEPS + r) * WPR + 1) * 4 + j] = (unsigned char)u;
        }
    }
    __syncthreads();

    // ---- phase 2: thread t owns columns 4t..4t+3, one STG.128 per (q,r) ----
    const int t = tid;
    if (t >= Q4) return;   // 294 active threads

    // per-element pair indices (i -> 48 = zero pad byte for diag)
    int ii[4], jj[4];
    #pragma unroll
    for (int e = 0; e < 4; ++e) {
        int k = 4 * t + e;
        if (k < AA) { ii[e] = AA; jj[e] = k; }
        else {
            int p = __ldg(&g_pair[k - AA]);
            ii[e] = p & 255;
            jj[e] = p >> 8;
        }
    }

    // segment decomposition: elements 0..es-1 from (iyA, baseA+e),
    // elements es..3 from (iyB, baseB+e); fast iff <= 2 segments
    int es = 4;
    bool fast = true;
    #pragma unroll
    for (int e = 1; e < 4; ++e) {
        bool cont = (ii[e] == ii[e - 1]) && (jj[e] == jj[e - 1] + 1);
        if (!cont) { if (es == 4) es = e; else fast = false; }
    }
    const int iyA   = ii[0];
    const int baseA = jj[0];
    const int iyB   = (es < 4) ? ii[es] : iyA;
    const int baseB = (es < 4) ? (jj[es] - es) : baseA;
    const int wA = baseA >> 2, shA = (baseA & 3) * 8;
    const int wB = baseB >> 2, shB = (baseB & 3) * 8;
    unsigned int selW = 0, selU = 0;
    #pragma unroll
    for (int e = 0; e < 4; ++e) {
        selW |= (unsigned int)((e < es) ? e : (4 + e)) << (4 * e);
        selU |= (unsigned int)((e < es) ? 0 : 1) << (4 * e);
    }
    // slow-path packed indices (rare: groups spanning 3 triangle rows)
    unsigned int iipk = 0, jjpk = 0;
    #pragma unroll
    for (int e = 0; e < 4; ++e) {
        iipk |= (unsigned int)ii[e] << (8 * e);
        jjpk |= (unsigned int)jj[e] << (8 * e);
    }

    const float* lut0 = g_lut + t * LUTW;

    float4* ob0 = reinterpret_cast<float4*>(
        out + ((long)(b0 + 0) * STEPS) * ROW) + t;
    float4* ob1 = reinterpret_cast<float4*>(
        out + ((long)(b0 + 1) * STEPS) * ROW) + t;

    // r outer, q inner-unrolled: two independent load->add->load->store chains
    for (int r = 0; r < STEPS; ++r) {
        #pragma unroll
        for (int q = 0; q < BPB; ++q) {
            const unsigned int* uw =
                s_state + (q * STEPS + r) * WPR + 1;
            const unsigned char* ub =
                reinterpret_cast<const unsigned char*>(uw);
            unsigned int sums;
            if (fast) {
                unsigned int uyA = ub[iyA];
                unsigned int uyB = ub[iyB];
                unsigned int a0 = uw[wA], a1 = uw[wA + 1];
                unsigned int b0w = uw[wB], b1w = uw[wB + 1];
                unsigned int alA = __funnelshift_r(a0, a1, shA);
                unsigned int alB = __funnelshift_r(b0w, b1w, shB);
                unsigned int comb = __byte_perm(alA, alB, selW);
                unsigned int uyv  = __byte_perm(uyA | (uyB << 8), 0, selU);
                sums = comb + uyv;            // 4 byte-sums, each <= 6
            } else {
                sums = 0;
                #pragma unroll
                for (int e = 0; e < 4; ++e) {
                    unsigned int s = (unsigned int)ub[(iipk >> (8 * e)) & 255]
                                   + (unsigned int)ub[(jjpk >> (8 * e)) & 255];
                    sums |= s << (8 * e);
                }
            }
            float4 vv;
            vv.x = __ldg(lut0 + 0 * LSZ + (sums         & 255u));
            vv.y = __ldg(lut0 + 1 * LSZ + ((sums >>  8) & 255u));
            vv.z = __ldg(lut0 + 2 * LSZ + ((sums >> 16) & 255u));
            vv.w = __ldg(lut0 + 3 * LSZ + ( sums >> 24        ));
            __stcs((q == 0 ? ob0 : ob1) + (long)r * Q4, vv);
        }
    }
}

extern "C" void kernel_launch(void* const* d_in, const int* in_sizes, int n_in,
                              void* d_out, int out_size) {
    const int*   x  = (const int*)d_in[0];     // (4096, 25, 48) int32
    const float* ed = (const float*)d_in[1];   // (1, 48) f32
    const float* en = (const float*)d_in[2];   // (1, 1128, 4) f32
    float* out = (float*)d_out;                // (4096, 23, 1176) f32

    setup_kernel<<<(NDP + 255) / 256, 256>>>(ed, en);
    int nb = in_sizes[0] / (25 * AA);          // 4096 batches
    main_kernel<<<nb / BPB, THREADS>>>(x, out);
}

// round 11
// speedup vs baseline: 1.0010x; 1.0010x over previous
#include <cuda_runtime.h>
#include <math.h>

#define AA 48
#define NDP 1128        // nondiag pairs
#define STEPS 23
#define ROW 1176        // AA + NDP
#define BPB 4           // batches per block
#define THREADS 320
#define Q4 (ROW / 4)    // 294 column-groups (one per thread)
#define LUTP 1184       // cls-stride (multiple of 32 -> conflict-free)
#define NCLS 7          // cls = u'i + u'j in 0..6, u' in {0,1,3}
#define WPR 13          // words per state row: [pad][12 data words]
#define NROWS (BPB * STEPS)

// transposed LUT: entry (k, cls) at cls*LUTP + (k&3)*Q4 + (k>>2)
__device__ float g_lut[NCLS * LUTP];
__device__ int   g_pair[NDP];        // iy | (ix<<8)

__global__ void setup_kernel(const float* __restrict__ ed,
                             const float* __restrict__ en) {
    int k = blockIdx.x * blockDim.x + threadIdx.x;
    if (k < AA) {
        // diag column k: i -> zero pad byte, so cls = u'j in {0,1,3}
        float s = 1.f / (1.f + expf(-ed[k]));
        int base = (k & 3) * Q4 + (k >> 2);
        #pragma unroll
        for (int c = 0; c < NCLS; ++c) {
            float v = (c == 1) ? s : (c == 3) ? 1.f : 0.f;
            g_lut[c * LUTP + base] = v;
        }
    }
    if (k < NDP) {
        float f12 = 1.f / (1.f + expf(-en[k * 4 + 0]));
        float f9  = 1.f / (1.f + expf(-en[k * 4 + 1])) * f12;
        float f8  = 1.f / (1.f + expf(-en[k * 4 + 2])) * f9;
        float f6  = 1.f / (1.f + expf(-en[k * 4 + 3])) * f8;
        // u' in {0,1,3}: cls -> 0:0  1:f6  2:f9  3:f8  4:f12  5:0  6:1
        float vals[NCLS] = {0.f, f6, f9, f8, f12, 0.f, 1.f};
        int kk = AA + k;
        int base = (kk & 3) * Q4 + (kk >> 2);
        #pragma unroll
        for (int c = 0; c < NCLS; ++c)
            g_lut[c * LUTP + base] = vals[c];
        int rem = k, iy = 0;
        while (rem >= AA - 1 - iy) { rem -= AA - 1 - iy; ++iy; }
        int ix = iy + 1 + rem;
        g_pair[k] = iy | (ix << 8);
    }
}

__global__ __launch_bounds__(THREADS, 6)
void main_kernel(const int* __restrict__ x, float* __restrict__ out) {
    __shared__ float        s_lut[NCLS * LUTP];            // 33152 B
    __shared__ unsigned int s_state[NROWS * WPR + 1];      //  4788 B

    const int tid = threadIdx.x;
    const int b0  = blockIdx.x * BPB;

    // ---- LUT copy (float4, 2072 vectors) ----
    {
        const float4* src = reinterpret_cast<const float4*>(g_lut);
        float4*       dst = reinterpret_cast<float4*>(s_lut);
        for (int i = tid; i < (NCLS * LUTP) / 4; i += THREADS)
            dst[i] = __ldg(src + i);
    }

    // ---- zero pad words: multiples of 13 (0..92*13 inclusive) ----
    if (tid <= NROWS) s_state[tid * WPR] = 0u;

    // ---- phase 1: integer recurrence, one thread per (q, column) ----
    if (tid < BPB * AA) {
        int q = tid / AA;
        int j = tid - q * AA;
        const int* xb = x + (long)(b0 + q) * (25 * AA) + j;
        unsigned int v = 0;
        #pragma unroll
        for (int r = 0; r < 25; ++r)
            v |= ((unsigned int)__ldg(xb + r * AA)) << r;

        unsigned char* sb = reinterpret_cast<unsigned char*>(s_state);
        int st = -1, dt = 1;
        #pragma unroll
        for (int r = 0; r < STEPS; ++r) {
            int a  = (v >> r)       & 1;
            int bb = (v >> (r + 1)) & 1;
            int c  = (v >> (r + 2)) & 1;
            int de = a ^ c;
            int me = bb * (1 - (a + c)) + a * c;
            dt = dt * (1 - 2 * me);
            st = st + dt * de;
            st = st < -1 ? -1 : (st > 1 ? 1 : st);
            int ome = 1 - me;
            dt = dt * (1 - st * st * ome) - st * ome;
            int u = st + 1;                 // 0,1,2
            u = u + (u >> 1);               // remap 2 -> 3 : u' in {0,1,3}
            sb[((q * STEPS + r) * WPR + 1) * 4 + j] = (unsigned char)u;
        }
    }
    __syncthreads();

    // ---- phase 2: thread t owns columns 4t..4t+3, one STG.128 per (q,r) ----
    const int t = tid;
    if (t >= Q4) return;   // 294 active threads

    // per-element pair indices (i -> 48 = zero pad byte for diag)
    int ii[4], jj[4];
    #pragma unroll
    for (int e = 0; e < 4; ++e) {
        int k = 4 * t + e;
        if (k < AA) { ii[e] = AA; jj[e] = k; }
        else {
            int p = __ldg(&g_pair[k - AA]);
            ii[e] = p & 255;
            jj[e] = p >> 8;
        }
    }

    // segment decomposition: elements 0..es-1 from (iyA, baseA+e),
    // elements es..3 from (iyB, baseB+e); fast iff <= 2 segments
    int es = 4;
    bool fast = true;
    #pragma unroll
    for (int e = 1; e < 4; ++e) {
        bool cont = (ii[e] == ii[e - 1]) && (jj[e] == jj[e - 1] + 1);
        if (!cont) { if (es == 4) es = e; else fast = false; }
    }
    const int iyA   = ii[0];
    const int baseA = jj[0];
    const int iyB   = (es < 4) ? ii[es] : iyA;
    const int baseB = (es < 4) ? (jj[es] - es) : baseA;
    const int wA = baseA >> 2, shA = (baseA & 3) * 8;
    const int wB = baseB >> 2, shB = (baseB & 3) * 8;  // baseB may be -1
    unsigned int selW = 0, selU = 0;
    #pragma unroll
    for (int e = 0; e < 4; ++e) {
        selW |= (unsigned int)((e < es) ? e : (4 + e)) << (4 * e);
        selU |= (unsigned int)((e < es) ? 0 : 1) << (4 * e);
    }
    // slow-path packed indices (rare: groups spanning 3 triangle rows)
    unsigned int iipk = 0, jjpk = 0;
    #pragma unroll
    for (int e = 0; e < 4; ++e) {
        iipk |= (unsigned int)ii[e] << (8 * e);
        jjpk |= (unsigned int)jj[e] << (8 * e);
    }

    float4* obase = reinterpret_cast<float4*>(
        out + ((long)b0 * STEPS) * ROW) + t;

    for (int q = 0; q < BPB; ++q) {
        float4* ob = obase + (long)q * (STEPS * Q4);
        for (int r = 0; r < STEPS; ++r) {
            const unsigned int* uw =
                s_state + (q * STEPS + r) * WPR + 1;
            const unsigned char* ub =
                reinterpret_cast<const unsigned char*>(uw);
            unsigned int sums;
            if (fast) {
                unsigned int uyA = ub[iyA];
                unsigned int uyB = ub[iyB];
                unsigned int a0 = uw[wA], a1 = uw[wA + 1];
                unsigned int b0w = uw[wB], b1w = uw[wB + 1];
                unsigned int alA = __funnelshift_r(a0, a1, shA);
                unsigned int alB = __funnelshift_r(b0w, b1w, shB);
                unsigned int comb = __byte_perm(alA, alB, selW);
                unsigned int uyv  = __byte_perm(uyA | (uyB << 8), 0, selU);
                sums = comb + uyv;            // 4 byte-sums, each <= 6
            } else {
                sums = 0;
                #pragma unroll
                for (int e = 0; e < 4; ++e) {
                    unsigned int s = (unsigned int)ub[(iipk >> (8 * e)) & 255]
                                   + (unsigned int)ub[(jjpk >> (8 * e)) & 255];
                    sums |= s << (8 * e);
                }
            }
            // conflict-free transposed LUT: bank = (e*294 + t) % 32
            float4 vv;
            vv.x = s_lut[(sums         & 255u) * LUTP + 0 * Q4 + t];
            vv.y = s_lut[((sums >>  8) & 255u) * LUTP + 1 * Q4 + t];
            vv.z = s_lut[((sums >> 16) & 255u) * LUTP + 2 * Q4 + t];
            vv.w = s_lut[( sums >> 24        ) * LUTP + 3 * Q4 + t];
            __stcs(ob + (long)r * Q4, vv);
        }
    }
}

extern "C" void kernel_launch(void* const* d_in, const int* in_sizes, int n_in,
                              void* d_out, int out_size) {
    const int*   x  = (const int*)d_in[0];     // (4096, 25, 48) int32
    const float* ed = (const float*)d_in[1];   // (1, 48) f32
    const float* en = (const float*)d_in[2];   // (1, 1128, 4) f32
    float* out = (float*)d_out;                // (4096, 23, 1176) f32

    setup_kernel<<<(NDP + 255) / 256, 256>>>(ed, en);
    int nb = in_sizes[0] / (25 * AA);          // 4096 batches
    main_kernel<<<nb / BPB, THREADS>>>(x, out);
}

// round 12
// speedup vs baseline: 1.2901x; 1.2888x over previous
#include <cuda_runtime.h>
#include <math.h>

#define AA 48
#define NDP 1128        // nondiag pairs
#define STEPS 23
#define ROW 1176        // AA + NDP
#define BPB 2           // batches per block
#define THREADS 320
#define Q4 (ROW / 4)    // 294 column-groups (one per thread)
#define LUTP 1184       // cls-stride (multiple of 32 -> conflict-free)
#define NCLS 7          // cls = u'i + u'j in 0..6, u' in {0,1,3}
#define WPR 13          // words per state row: [pad][12 data words]
#define NROWS (BPB * STEPS)

// transposed LUT: entry (k, cls) at cls*LUTP + (k&3)*Q4 + (k>>2)
__device__ float g_lut[NCLS * LUTP];
__device__ int   g_pair[NDP];        // iy | (ix<<8)

__global__ void setup_kernel(const float* __restrict__ ed,
                             const float* __restrict__ en) {
    int k = blockIdx.x * blockDim.x + threadIdx.x;
    if (k < AA) {
        // diag column k: i -> zero pad byte, so cls = u'j in {0,1,3}
        float s = 1.f / (1.f + expf(-ed[k]));
        int base = (k & 3) * Q4 + (k >> 2);
        #pragma unroll
        for (int c = 0; c < NCLS; ++c) {
            float v = (c == 1) ? s : (c == 3) ? 1.f : 0.f;
            g_lut[c * LUTP + base] = v;
        }
    }
    if (k < NDP) {
        float f12 = 1.f / (1.f + expf(-en[k * 4 + 0]));
        float f9  = 1.f / (1.f + expf(-en[k * 4 + 1])) * f12;
        float f8  = 1.f / (1.f + expf(-en[k * 4 + 2])) * f9;
        float f6  = 1.f / (1.f + expf(-en[k * 4 + 3])) * f8;
        // u' in {0,1,3}: cls -> 0:0  1:f6  2:f9  3:f8  4:f12  5:0  6:1
        float vals[NCLS] = {0.f, f6, f9, f8, f12, 0.f, 1.f};
        int kk = AA + k;
        int base = (kk & 3) * Q4 + (kk >> 2);
        #pragma unroll
        for (int c = 0; c < NCLS; ++c)
            g_lut[c * LUTP + base] = vals[c];
        int rem = k, iy = 0;
        while (rem >= AA - 1 - iy) { rem -= AA - 1 - iy; ++iy; }
        int ix = iy + 1 + rem;
        g_pair[k] = iy | (ix << 8);
    }
}

__global__ __launch_bounds__(THREADS, 6)
void main_kernel(const int* __restrict__ x, float* __restrict__ out) {
    __shared__ float        s_lut[NCLS * LUTP];            // 33152 B
    __shared__ unsigned int s_state[NROWS * WPR + 1];      //  2396 B

    const int tid = threadIdx.x;
    const int b0  = blockIdx.x * BPB;

    // ---- LUT copy (float4, 2072 vectors) ----
    {
        const float4* src = reinterpret_cast<const float4*>(g_lut);
        float4*       dst = reinterpret_cast<float4*>(s_lut);
        for (int i = tid; i < (NCLS * LUTP) / 4; i += THREADS)
            dst[i] = __ldg(src + i);
    }

    // ---- zero pad words: multiples of 13 ----
    if (tid <= NROWS) s_state[tid * WPR] = 0u;

    // ---- phase 1: integer recurrence, one thread per (q, column) ----
    if (tid < BPB * AA) {
        int q = tid / AA;
        int j = tid - q * AA;
        const int* xb = x + (long)(b0 + q) * (25 * AA) + j;
        unsigned int v = 0;
        #pragma unroll
        for (int r = 0; r < 25; ++r)
            v |= ((unsigned int)__ldg(xb + r * AA)) << r;

        unsigned char* sb = reinterpret_cast<unsigned char*>(s_state);
        int st = -1, dt = 1;
        #pragma unroll
        for (int r = 0; r < STEPS; ++r) {
            int a  = (v >> r)       & 1;
            int bb = (v >> (r + 1)) & 1;
            int c  = (v >> (r + 2)) & 1;
            int de = a ^ c;
            int me = bb * (1 - (a + c)) + a * c;
            dt = dt * (1 - 2 * me);
            st = st + dt * de;
            st = st < -1 ? -1 : (st > 1 ? 1 : st);
            int ome = 1 - me;
            dt = dt * (1 - st * st * ome) - st * ome;
            int u = st + 1;                 // 0,1,2
            u = u + (u >> 1);               // remap 2 -> 3 : u' in {0,1,3}
            sb[((q * STEPS + r) * WPR + 1) * 4 + j] = (unsigned char)u;
        }
    }
    __syncthreads();

    // ---- phase 2: thread t owns columns 4t..4t+3, one STG.128 per (q,r) ----
    const int t = tid;
    if (t >= Q4) return;   // 294 active threads

    // per-element pair indices (i -> 48 = zero pad byte for diag)
    int ii[4], jj[4];
    #pragma unroll
    for (int e = 0; e < 4; ++e) {
        int k = 4 * t + e;
        if (k < AA) { ii[e] = AA; jj[e] = k; }
        else {
            int p = __ldg(&g_pair[k - AA]);
            ii[e] = p & 255;
            jj[e] = p >> 8;
        }
    }

    // segment decomposition: elements 0..es-1 from (iyA, baseA+e),
    // elements es..3 from (iyB, baseB+e); fast iff <= 2 segments
    int es = 4;
    bool fast = true;
    #pragma unroll
    for (int e = 1; e < 4; ++e) {
        bool cont = (ii[e] == ii[e - 1]) && (jj[e] == jj[e - 1] + 1);
        if (!cont) { if (es == 4) es = e; else fast = false; }
    }
    const int iyA   = ii[0];
    const int baseA = jj[0];
    const int iyB   = (es < 4) ? ii[es] : iyA;
    const int baseB = (es < 4) ? (jj[es] - es) : baseA;
    const int wA = baseA >> 2, shA = (baseA & 3) * 8;
    const int wB = baseB >> 2, shB = (baseB & 3) * 8;  // baseB may be -1
    unsigned int selW = 0, selU = 0;
    #pragma unroll
    for (int e = 0; e < 4; ++e) {
        selW |= (unsigned int)((e < es) ? e : (4 + e)) << (4 * e);
        selU |= (unsigned int)((e < es) ? 0 : 1) << (4 * e);
    }
    // slow-path packed indices (rare: groups spanning 3 triangle rows)
    unsigned int iipk = 0, jjpk = 0;
    #pragma unroll
    for (int e = 0; e < 4; ++e) {
        iipk |= (unsigned int)ii[e] << (8 * e);
        jjpk |= (unsigned int)jj[e] << (8 * e);
    }

    float4* obase = reinterpret_cast<float4*>(
        out + ((long)b0 * STEPS) * ROW) + t;

    for (int q = 0; q < BPB; ++q) {
        float4* ob = obase + (long)q * (STEPS * Q4);
        for (int r = 0; r < STEPS; ++r) {
            const unsigned int* uw =
                s_state + (q * STEPS + r) * WPR + 1;
            const unsigned char* ub =
                reinterpret_cast<const unsigned char*>(uw);
            unsigned int sums;
            if (fast) {
                unsigned int uyA = ub[iyA];
                unsigned int uyB = ub[iyB];
                unsigned int a0 = uw[wA], a1 = uw[wA + 1];
                unsigned int b0w = uw[wB], b1w = uw[wB + 1];
                unsigned int alA = __funnelshift_r(a0, a1, shA);
                unsigned int alB = __funnelshift_r(b0w, b1w, shB);
                unsigned int comb = __byte_perm(alA, alB, selW);
                unsigned int uyv  = __byte_perm(uyA | (uyB << 8), 0, selU);
                sums = comb + uyv;            // 4 byte-sums, each <= 6
            } else {
                sums = 0;
                #pragma unroll
                for (int e = 0; e < 4; ++e) {
                    unsigned int s = (unsigned int)ub[(iipk >> (8 * e)) & 255]
                                   + (unsigned int)ub[(jjpk >> (8 * e)) & 255];
                    sums |= s << (8 * e);
                }
            }
            // conflict-free transposed LUT: bank = (e*294 + t) % 32
            float4 vv;
            vv.x = s_lut[(sums         & 255u) * LUTP + 0 * Q4 + t];
            vv.y = s_lut[((sums >>  8) & 255u) * LUTP + 1 * Q4 + t];
            vv.z = s_lut[((sums >> 16) & 255u) * LUTP + 2 * Q4 + t];
            vv.w = s_lut[( sums >> 24        ) * LUTP + 3 * Q4 + t];
            __stcs(ob + (long)r * Q4, vv);
        }
    }
}

extern "C" void kernel_launch(void* const* d_in, const int* in_sizes, int n_in,
                              void* d_out, int out_size) {
    const int*   x  = (const int*)d_in[0];     // (4096, 25, 48) int32
    const float* ed = (const float*)d_in[1];   // (1, 48) f32
    const float* en = (const float*)d_in[2];   // (1, 1128, 4) f32
    float* out = (float*)d_out;                // (4096, 23, 1176) f32

    setup_kernel<<<(NDP + 255) / 256, 256>>>(ed, en);
    int nb = in_sizes[0] / (25 * AA);          // 4096 batches
    main_kernel<<<nb / BPB, THREADS>>>(x, out);
}

// round 13
// speedup vs baseline: 1.3534x; 1.0491x over previous
#include <cuda_runtime.h>
#include <math.h>

#define AA 48
#define NDP 1128        // nondiag pairs
#define STEPS 23
#define ROW 1176        // AA + NDP
#define BPB 2           // batches per block
#define THREADS 320
#define Q4 (ROW / 4)    // 294 column-groups (one per thread)
#define LUTP 1184       // cls-stride (multiple of 32 -> conflict-free)
#define NCLS 6          // compact classes 0..5 (orig cls 6 -> 5 via vmin)
#define WPR 13          // words per state row: [pad][12 data words]
#define NROWS (BPB * STEPS)

// transposed LUT: entry (k, cls) at cls*LUTP + (k&3)*Q4 + (k>>2)
__device__ float g_lut[NCLS * LUTP];
__device__ int   g_pair[NDP];        // iy | (ix<<8)

__global__ void setup_kernel(const float* __restrict__ ed,
                             const float* __restrict__ en) {
    int k = blockIdx.x * blockDim.x + threadIdx.x;
    if (k < AA) {
        // diag column k: i -> zero pad byte, so cls = u'j in {0,1,3}
        float s = 1.f / (1.f + expf(-ed[k]));
        int base = (k & 3) * Q4 + (k >> 2);
        #pragma unroll
        for (int c = 0; c < NCLS; ++c) {
            float v = (c == 1) ? s : (c == 3) ? 1.f : 0.f;
            g_lut[c * LUTP + base] = v;
        }
    }
    if (k < NDP) {
        float f12 = 1.f / (1.f + expf(-en[k * 4 + 0]));
        float f9  = 1.f / (1.f + expf(-en[k * 4 + 1])) * f12;
        float f8  = 1.f / (1.f + expf(-en[k * 4 + 2])) * f9;
        float f6  = 1.f / (1.f + expf(-en[k * 4 + 3])) * f8;
        // u' in {0,1,3}: cls(min5) -> 0:0  1:f6  2:f9  3:f8  4:f12  5:1
        float vals[NCLS] = {0.f, f6, f9, f8, f12, 1.f};
        int kk = AA + k;
        int base = (kk & 3) * Q4 + (kk >> 2);
        #pragma unroll
        for (int c = 0; c < NCLS; ++c)
            g_lut[c * LUTP + base] = vals[c];
        int rem = k, iy = 0;
        while (rem >= AA - 1 - iy) { rem -= AA - 1 - iy; ++iy; }
        int ix = iy + 1 + rem;
        g_pair[k] = iy | (ix << 8);
    }
}

__global__ __launch_bounds__(THREADS, 6)
void main_kernel(const int* __restrict__ x, float* __restrict__ out) {
    __shared__ float        s_lut[NCLS * LUTP];            // 28416 B
    __shared__ unsigned int s_state[NROWS * WPR + 1];      //  2396 B

    const int tid = threadIdx.x;
    const int b0  = blockIdx.x * BPB;

    // ---- LUT copy (float4, 1776 vectors) ----
    {
        const float4* src = reinterpret_cast<const float4*>(g_lut);
        float4*       dst = reinterpret_cast<float4*>(s_lut);
        for (int i = tid; i < (NCLS * LUTP) / 4; i += THREADS)
            dst[i] = __ldg(src + i);
    }

    // ---- zero pad words: multiples of 13 ----
    if (tid <= NROWS) s_state[tid * WPR] = 0u;

    // ---- phase 1: integer recurrence, one thread per (q, column) ----
    if (tid < BPB * AA) {
        int q = tid / AA;
        int j = tid - q * AA;
        const int* xb = x + (long)(b0 + q) * (25 * AA) + j;
        unsigned int v = 0;
        #pragma unroll
        for (int r = 0; r < 25; ++r)
            v |= ((unsigned int)__ldg(xb + r * AA)) << r;

        unsigned char* sb = reinterpret_cast<unsigned char*>(s_state);
        int st = -1, dt = 1;
        #pragma unroll
        for (int r = 0; r < STEPS; ++r) {
            int a  = (v >> r)       & 1;
            int bb = (v >> (r + 1)) & 1;
            int c  = (v >> (r + 2)) & 1;
            int de = a ^ c;
            int me = bb * (1 - (a + c)) + a * c;
            dt = dt * (1 - 2 * me);
            st = st + dt * de;
            st = st < -1 ? -1 : (st > 1 ? 1 : st);
            int ome = 1 - me;
            dt = dt * (1 - st * st * ome) - st * ome;
            int u = st + 1;                 // 0,1,2
            u = u + (u >> 1);               // remap 2 -> 3 : u' in {0,1,3}
            sb[((q * STEPS + r) * WPR + 1) * 4 + j] = (unsigned char)u;
        }
    }
    __syncthreads();

    // ---- phase 2: thread t owns columns 4t..4t+3, one STG.128 per (q,r) ----
    const int t = tid;
    if (t >= Q4) return;   // 294 active threads

    // per-element pair indices (i -> 48 = zero pad byte for diag)
    int ii[4], jj[4];
    #pragma unroll
    for (int e = 0; e < 4; ++e) {
        int k = 4 * t + e;
        if (k < AA) { ii[e] = AA; jj[e] = k; }
        else {
            int p = __ldg(&g_pair[k - AA]);
            ii[e] = p & 255;
            jj[e] = p >> 8;
        }
    }

    // segment decomposition: elements 0..es-1 from (iyA, baseA+e),
    // elements es..3 from (iyB, baseB+e); fast iff <= 2 segments
    int es = 4;
    bool fast = true;
    #pragma unroll
    for (int e = 1; e < 4; ++e) {
        bool cont = (ii[e] == ii[e - 1]) && (jj[e] == jj[e - 1] + 1);
        if (!cont) { if (es == 4) es = e; else fast = false; }
    }
    const bool single = (es == 4);
    const int iyA   = ii[0];
    const int baseA = jj[0];
    const int iyB   = single ? iyA : ii[es];
    const int baseB = single ? baseA : (jj[es] - es);
    const int wA = baseA >> 2, shA = (baseA & 3) * 8;
    const int wB = baseB >> 2, shB = (baseB & 3) * 8;  // baseB may be < 0
    unsigned int selW = 0, selU = 0;
    #pragma unroll
    for (int e = 0; e < 4; ++e) {
        selW |= (unsigned int)((e < es) ? e : (4 + e)) << (4 * e);
        selU |= (unsigned int)((e < es) ? 0 : 1) << (4 * e);
    }
    // slow-path packed indices (rare: groups spanning 3 triangle rows)
    unsigned int iipk = 0, jjpk = 0;
    #pragma unroll
    for (int e = 0; e < 4; ++e) {
        iipk |= (unsigned int)ii[e] << (8 * e);
        jjpk |= (unsigned int)jj[e] << (8 * e);
    }

    float4* obase = reinterpret_cast<float4*>(
        out + ((long)b0 * STEPS) * ROW) + t;

    for (int q = 0; q < BPB; ++q) {
        float4* ob = obase + (long)q * (STEPS * Q4);
        for (int r = 0; r < STEPS; ++r) {
            const unsigned int* uw =
                s_state + (q * STEPS + r) * WPR + 1;
            const unsigned char* ub =
                reinterpret_cast<const unsigned char*>(uw);
            unsigned int sums;
            if (fast) {
                unsigned int uyA = ub[iyA];
                unsigned int alA =
                    __funnelshift_r(uw[wA], uw[wA + 1], shA);
                unsigned int alB, uyB;
                if (single) { alB = alA; uyB = uyA; }
                else {
                    alB = __funnelshift_r(uw[wB], uw[wB + 1], shB);
                    uyB = ub[iyB];
                }
                unsigned int comb = __byte_perm(alA, alB, selW);
                unsigned int uyv  = __byte_perm(uyA | (uyB << 8), 0, selU);
                sums = comb + uyv;            // 4 byte-sums, each <= 6
            } else {
                sums = 0;
                #pragma unroll
                for (int e = 0; e < 4; ++e) {
                    unsigned int s = (unsigned int)ub[(iipk >> (8 * e)) & 255]
                                   + (unsigned int)ub[(jjpk >> (8 * e)) & 255];
                    sums |= s << (8 * e);
                }
            }
            sums = __vminu4(sums, 0x05050505u);   // cls 6 -> 5 (compact LUT)
            // conflict-free transposed LUT: bank = (e*294 + t) % 32
            float4 vv;
            vv.x = s_lut[(sums         & 255u) * LUTP + 0 * Q4 + t];
            vv.y = s_lut[((sums >>  8) & 255u) * LUTP + 1 * Q4 + t];
            vv.z = s_lut[((sums >> 16) & 255u) * LUTP + 2 * Q4 + t];
            vv.w = s_lut[( sums >> 24        ) * LUTP + 3 * Q4 + t];
            __stcs(ob + (long)r * Q4, vv);
        }
    }
}

extern "C" void kernel_launch(void* const* d_in, const int* in_sizes, int n_in,
                              void* d_out, int out_size) {
    const int*   x  = (const int*)d_in[0];     // (4096, 25, 48) int32
    const float* ed = (const float*)d_in[1];   // (1, 48) f32
    const float* en = (const float*)d_in[2];   // (1, 1128, 4) f32
    float* out = (float*)d_out;                // (4096, 23, 1176) f32

    setup_kernel<<<(NDP + 255) / 256, 256>>>(ed, en);
    int nb = in_sizes[0] / (25 * AA);          // 4096 batches
    main_kernel<<<nb / BPB, THREADS>>>(x, out);
}